// round 13
// baseline (speedup 1.0000x reference)
#include <cuda_runtime.h>
#include <cuda_fp16.h>
#include <cstdint>

// Problem constants (match reference_code)
#define N_NODES 150000
#define DIM 64
#define NE 4800000
#define LN_EPS 1e-5f
#define LEAKY_SLOPE 0.5f
#define SCAN_B 1024
#define NB 147            // ceil(150000/1024)
#define NGRID 587         // ceil(150000/256)

// Per-SpMM scale folded into edge weights so fp16 intermediates never overflow.
// 6 SpMMs => final h is (1/16)^6 = 2^-24 of true value; LN kernel undoes it.
#define VAL_SCALE  0.0625f            // 1/16
#define UNSCALE    16777216.0f        // 2^24
#define VAL_DEC    (VAL_SCALE / 16384.0f)   // decode 14-bit fixed-point -> scaled val

// ---------------- device scratch (no allocation allowed) -------------------
__device__ __align__(16) __half g_tmp_h[(size_t)N_NODES * DIM];
__device__ __align__(16) __half g_hh   [(size_t)N_NODES * DIM];
__device__ __align__(16) __half g_ego_h[(size_t)N_NODES * DIM];

__device__ int  g_cnt_r[N_NODES], g_cnt_c[N_NODES];
__device__ int  g_ptr_r[N_NODES + 1], g_ptr_c[N_NODES + 1];   // ptr[N] = NE
__device__ int  g_cur_r[N_NODES], g_cur_c[N_NODES];
__device__ int  g_bsum_r[NB], g_bsum_c[NB];
// packed edges: (nbr << 14) | val14  = 4 B each, 16-B aligned for uint4 loads
__device__ __align__(16) unsigned int g_edge_r[NE];
__device__ __align__(16) unsigned int g_edge_c[NE];

// ---------------------------------------------------------------------------
// zero counts + ego->fp16 conversion fused (grid-stride on the cvt part).
// Also makes spmm0 the 6th launch so ncu (-s 5 -c 1) finally profiles it.
// ---------------------------------------------------------------------------
__global__ __launch_bounds__(256) void zero_cvt(
    int* __restrict__ a, int* __restrict__ b,
    const float4* __restrict__ in, uint2* __restrict__ out)
{
    int i = blockIdx.x * blockDim.x + threadIdx.x;
    if (i < N_NODES) { a[i] = 0; b[i] = 0; }
    const int n4 = N_NODES * DIM / 4;          // 2.4M
    for (int k = i; k < n4; k += NGRID * 256) {
        float4 f = __ldg(in + k);
        __half2 p0 = __floats2half2_rn(f.x, f.y);
        __half2 p1 = __floats2half2_rn(f.z, f.w);
        uint2 o;
        o.x = *reinterpret_cast<unsigned int*>(&p0);
        o.y = *reinterpret_cast<unsigned int*>(&p1);
        out[k] = o;
    }
}

// histogram: 4 edges per thread via int4 loads
__global__ __launch_bounds__(256) void hist_kernel4(
    const int4* __restrict__ rows4, const int4* __restrict__ cols4,
    int* __restrict__ cnt_r, int* __restrict__ cnt_c)
{
    int i = blockIdx.x * blockDim.x + threadIdx.x;
    if (i >= NE / 4) return;
    int4 r = __ldg(rows4 + i);
    int4 c = __ldg(cols4 + i);
    atomicAdd(cnt_r + r.x, 1); atomicAdd(cnt_r + r.y, 1);
    atomicAdd(cnt_r + r.z, 1); atomicAdd(cnt_r + r.w, 1);
    atomicAdd(cnt_c + c.x, 1); atomicAdd(cnt_c + c.y, 1);
    atomicAdd(cnt_c + c.z, 1); atomicAdd(cnt_c + c.w, 1);
}

// per-block exclusive scan; handles BOTH cnt arrays in one launch (2*NB blocks)
__global__ __launch_bounds__(SCAN_B) void scan1_both(
    const int* __restrict__ cnt_r, int* __restrict__ excl_r, int* __restrict__ bsum_r,
    const int* __restrict__ cnt_c, int* __restrict__ excl_c, int* __restrict__ bsum_c)
{
    const int which = blockIdx.x / NB;
    const int blk   = blockIdx.x - which * NB;
    const int* cnt  = which ? cnt_c  : cnt_r;
    int* excl       = which ? excl_c : excl_r;
    int* bsum       = which ? bsum_c : bsum_r;

    __shared__ int sh[SCAN_B];
    int tid = threadIdx.x;
    int i   = blk * SCAN_B + tid;
    int v   = (i < N_NODES) ? cnt[i] : 0;
    sh[tid] = v;
    __syncthreads();
    #pragma unroll
    for (int off = 1; off < SCAN_B; off <<= 1) {
        int t = (tid >= off) ? sh[tid - off] : 0;
        __syncthreads();
        sh[tid] += t;
        __syncthreads();
    }
    if (i < N_NODES) excl[i] = sh[tid] - v;
    if (tid == SCAN_B - 1) bsum[blk] = sh[tid];
}

// fused scan2+scan3: every 256-node chunk redundantly scans the 147 block
// sums in shared, then applies and initializes cursor; writes ptr[N]=NE.
__global__ __launch_bounds__(256) void scan23_both(
    int* __restrict__ excl_r, const int* __restrict__ bsum_r, int* __restrict__ cur_r,
    int* __restrict__ excl_c, const int* __restrict__ bsum_c, int* __restrict__ cur_c,
    int ngrid)
{
    const int which = blockIdx.x / ngrid;
    const int blk   = blockIdx.x - which * ngrid;
    int* excl       = which ? excl_c : excl_r;
    const int* bsum = which ? bsum_c : bsum_r;
    int* cursor     = which ? cur_c  : cur_r;

    __shared__ int sh[256];
    int tid = threadIdx.x;
    int v   = (tid < NB) ? __ldg(bsum + tid) : 0;
    sh[tid] = v;
    __syncthreads();
    #pragma unroll
    for (int off = 1; off < 256; off <<= 1) {
        int t = (tid >= off) ? sh[tid - off] : 0;
        __syncthreads();
        sh[tid] += t;
        __syncthreads();
    }
    int b   = (blk * 256) >> 10;               // constant within this chunk
    int add = sh[b] - __ldg(bsum + b);         // exclusive prefix of block b
    int i   = blk * 256 + tid;
    if (i < N_NODES) {
        int val = excl[i] + add;
        excl[i]   = val;
        cursor[i] = val;
    }
    if (blk == 0 && tid == 0) excl[N_NODES] = NE;   // sentinel: ptr[N] = NE
}

// pack an edge: (nbr << 14) | round(val * 16384), val in [0,1)
__device__ __forceinline__ unsigned int pack_edge(int nbr, float val) {
    unsigned int v14 = (unsigned int)(val * 16384.0f + 0.5f);
    v14 = v14 > 16383u ? 16383u : v14;
    return ((unsigned int)nbr << 14) | v14;
}

// scatter packed edges (4 edges/thread)
__global__ __launch_bounds__(256) void fill_kernel4(
    const int4* __restrict__ rows4, const int4* __restrict__ cols4,
    const float4* __restrict__ vals4,
    int* __restrict__ cur_r, int* __restrict__ cur_c,
    unsigned int* __restrict__ edge_r, unsigned int* __restrict__ edge_c)
{
    int i = blockIdx.x * blockDim.x + threadIdx.x;
    if (i >= NE / 4) return;
    int4   r = __ldg(rows4 + i);
    int4   c = __ldg(cols4 + i);
    float4 v = __ldg(vals4 + i);

    edge_r[atomicAdd(cur_r + r.x, 1)] = pack_edge(c.x, v.x);
    edge_r[atomicAdd(cur_r + r.y, 1)] = pack_edge(c.y, v.y);
    edge_r[atomicAdd(cur_r + r.z, 1)] = pack_edge(c.z, v.z);
    edge_r[atomicAdd(cur_r + r.w, 1)] = pack_edge(c.w, v.w);
    edge_c[atomicAdd(cur_c + c.x, 1)] = pack_edge(r.x, v.x);
    edge_c[atomicAdd(cur_c + c.y, 1)] = pack_edge(r.y, v.y);
    edge_c[atomicAdd(cur_c + c.z, 1)] = pack_edge(r.z, v.z);
    edge_c[atomicAdd(cur_c + c.w, 1)] = pack_edge(r.w, v.w);
}

// ---------------------------------------------------------------------------
// Core per-edge accumulate: 16 B (8 halves) -> 8 fp32 accs
// ---------------------------------------------------------------------------
__device__ __forceinline__ void accum_u4(uint4 p, float v, bool leaky, float* a) {
    __half2 h0 = *reinterpret_cast<__half2*>(&p.x);
    __half2 h1 = *reinterpret_cast<__half2*>(&p.y);
    __half2 h2 = *reinterpret_cast<__half2*>(&p.z);
    __half2 h3 = *reinterpret_cast<__half2*>(&p.w);
    if (leaky) {
        const __half2 h05 = __float2half2_rn(LEAKY_SLOPE);
        h0 = __hmax2(h0, __hmul2(h0, h05));
        h1 = __hmax2(h1, __hmul2(h1, h05));
        h2 = __hmax2(h2, __hmul2(h2, h05));
        h3 = __hmax2(h3, __hmul2(h3, h05));
    }
    float2 f0 = __half22float2(h0);
    float2 f1 = __half22float2(h1);
    float2 f2 = __half22float2(h2);
    float2 f3 = __half22float2(h3);
    a[0] = fmaf(v, f0.x, a[0]);
    a[1] = fmaf(v, f0.y, a[1]);
    a[2] = fmaf(v, f1.x, a[2]);
    a[3] = fmaf(v, f1.y, a[3]);
    a[4] = fmaf(v, f2.x, a[4]);
    a[5] = fmaf(v, f2.y, a[5]);
    a[6] = fmaf(v, f3.x, a[6]);
    a[7] = fmaf(v, f3.y, a[7]);
}

__device__ __forceinline__ float edge_val(unsigned int e) {
    return (float)(e & 0x3FFFu) * VAL_DEC;
}

// ---------------------------------------------------------------------------
// Gather SpMM (fp16 node data, fp32 accumulate):
//   8 lanes per node, each lane owns 16 B; packed 4-B edges, uint4 = 4 edges;
//   8-edge unroll -> 8 concurrent gathers per group, 32 per warp.
// ---------------------------------------------------------------------------
template <bool LEAKY_IN>
__global__ __launch_bounds__(256) void spmm_gather_h8(
    const uint4*        __restrict__ x,      // fp16 rows: node*8 + lane
    const int*          __restrict__ ptr,    // N+1 entries (ptr[N] = NE)
    const unsigned int* __restrict__ edges,  // packed
    uint4*              __restrict__ y)
{
    int t    = blockIdx.x * blockDim.x + threadIdx.x;
    int node = t >> 3;
    int lane = t & 7;
    if (node >= N_NODES) return;

    int beg = __ldg(ptr + node);
    int end = __ldg(ptr + node + 1);

    float acc[8] = {0.f, 0.f, 0.f, 0.f, 0.f, 0.f, 0.f, 0.f};

    int j = beg;
    // peel to 4-edge (16 B) alignment
    while ((j & 3) && j < end) {
        unsigned int e = __ldcs(edges + j);
        uint4 p = __ldg(x + (e >> 14) * 8 + lane);
        accum_u4(p, edge_val(e), LEAKY_IN, acc);
        ++j;
    }
    // 8-edge unroll: 2 aligned uint4 edge loads + 8 independent gathers
    for (; j + 8 <= end; j += 8) {
        uint4 ea = __ldcs(reinterpret_cast<const uint4*>(edges + j));
        uint4 eb = __ldcs(reinterpret_cast<const uint4*>(edges + j + 4));
        uint4 p0 = __ldg(x + (ea.x >> 14) * 8 + lane);
        uint4 p1 = __ldg(x + (ea.y >> 14) * 8 + lane);
        uint4 p2 = __ldg(x + (ea.z >> 14) * 8 + lane);
        uint4 p3 = __ldg(x + (ea.w >> 14) * 8 + lane);
        uint4 p4 = __ldg(x + (eb.x >> 14) * 8 + lane);
        uint4 p5 = __ldg(x + (eb.y >> 14) * 8 + lane);
        uint4 p6 = __ldg(x + (eb.z >> 14) * 8 + lane);
        uint4 p7 = __ldg(x + (eb.w >> 14) * 8 + lane);
        accum_u4(p0, edge_val(ea.x), LEAKY_IN, acc);
        accum_u4(p1, edge_val(ea.y), LEAKY_IN, acc);
        accum_u4(p2, edge_val(ea.z), LEAKY_IN, acc);
        accum_u4(p3, edge_val(ea.w), LEAKY_IN, acc);
        accum_u4(p4, edge_val(eb.x), LEAKY_IN, acc);
        accum_u4(p5, edge_val(eb.y), LEAKY_IN, acc);
        accum_u4(p6, edge_val(eb.z), LEAKY_IN, acc);
        accum_u4(p7, edge_val(eb.w), LEAKY_IN, acc);
    }
    if (j + 4 <= end) {
        uint4 ea = __ldcs(reinterpret_cast<const uint4*>(edges + j));
        uint4 p0 = __ldg(x + (ea.x >> 14) * 8 + lane);
        uint4 p1 = __ldg(x + (ea.y >> 14) * 8 + lane);
        uint4 p2 = __ldg(x + (ea.z >> 14) * 8 + lane);
        uint4 p3 = __ldg(x + (ea.w >> 14) * 8 + lane);
        accum_u4(p0, edge_val(ea.x), LEAKY_IN, acc);
        accum_u4(p1, edge_val(ea.y), LEAKY_IN, acc);
        accum_u4(p2, edge_val(ea.z), LEAKY_IN, acc);
        accum_u4(p3, edge_val(ea.w), LEAKY_IN, acc);
        j += 4;
    }
    while (j < end) {
        unsigned int e = __ldcs(edges + j);
        uint4 p = __ldg(x + (e >> 14) * 8 + lane);
        accum_u4(p, edge_val(e), LEAKY_IN, acc);
        ++j;
    }

    __half2 o0 = __floats2half2_rn(acc[0], acc[1]);
    __half2 o1 = __floats2half2_rn(acc[2], acc[3]);
    __half2 o2 = __floats2half2_rn(acc[4], acc[5]);
    __half2 o3 = __floats2half2_rn(acc[6], acc[7]);
    uint4 o;
    o.x = *reinterpret_cast<unsigned int*>(&o0);
    o.y = *reinterpret_cast<unsigned int*>(&o1);
    o.z = *reinterpret_cast<unsigned int*>(&o2);
    o.w = *reinterpret_cast<unsigned int*>(&o3);
    y[node * 8 + lane] = o;
}

// ---------------------------------------------------------------------------
// Final: out = LN(h * 2^24) * gamma + beta + ego   (warp per node, D=64)
// ---------------------------------------------------------------------------
__global__ __launch_bounds__(256) void ln_residual_kernel(
    const __half2* __restrict__ h,
    const float2*  __restrict__ ego,
    const float*   __restrict__ gamma,
    const float*   __restrict__ beta,
    float2*        __restrict__ out)
{
    int gt   = blockIdx.x * blockDim.x + threadIdx.x;
    int node = gt >> 5;
    int lane = threadIdx.x & 31;
    if (node >= N_NODES) return;

    int idx = node * 32 + lane;
    float2 v = __half22float2(h[idx]);
    v.x *= UNSCALE;
    v.y *= UNSCALE;

    float s = v.x + v.y;
    #pragma unroll
    for (int o = 16; o; o >>= 1) s += __shfl_xor_sync(0xFFFFFFFFu, s, o);
    float mu = s * (1.f / 64.f);

    float dx = v.x - mu, dy = v.y - mu;
    float q = dx * dx + dy * dy;
    #pragma unroll
    for (int o = 16; o; o >>= 1) q += __shfl_xor_sync(0xFFFFFFFFu, q, o);
    float rstd = rsqrtf(q * (1.f / 64.f) + LN_EPS);

    float2 g = __ldg((const float2*)gamma + lane);
    float2 b = __ldg((const float2*)beta  + lane);
    float2 r = ego[idx];

    float2 o2;
    o2.x = dx * rstd * g.x + b.x + r.x;
    o2.y = dy * rstd * g.y + b.y + r.y;
    out[idx] = o2;
}

// ---------------------------------------------------------------------------
extern "C" void kernel_launch(void* const* d_in, const int* in_sizes, int n_in,
                              void* d_out, int out_size)
{
    const float* ego   = (const float*)d_in[0];
    const float* vals  = (const float*)d_in[1];
    const float* gamma = (const float*)d_in[2];
    const float* beta  = (const float*)d_in[3];
    const int*   rows  = (const int*)d_in[4];
    const int*   cols  = (const int*)d_in[5];
    float*       out   = (float*)d_out;

    void *tmp_h, *hh, *ego_h;
    int *cnt_r, *cnt_c, *ptr_r, *ptr_c, *cur_r, *cur_c, *bsum_r, *bsum_c;
    unsigned int *edge_r, *edge_c;
    cudaGetSymbolAddress(&tmp_h, g_tmp_h);
    cudaGetSymbolAddress(&hh,    g_hh);
    cudaGetSymbolAddress(&ego_h, g_ego_h);
    cudaGetSymbolAddress((void**)&cnt_r,  g_cnt_r);
    cudaGetSymbolAddress((void**)&cnt_c,  g_cnt_c);
    cudaGetSymbolAddress((void**)&ptr_r,  g_ptr_r);
    cudaGetSymbolAddress((void**)&ptr_c,  g_ptr_c);
    cudaGetSymbolAddress((void**)&cur_r,  g_cur_r);
    cudaGetSymbolAddress((void**)&cur_c,  g_cur_c);
    cudaGetSymbolAddress((void**)&bsum_r, g_bsum_r);
    cudaGetSymbolAddress((void**)&bsum_c, g_bsum_c);
    cudaGetSymbolAddress((void**)&edge_r, g_edge_r);
    cudaGetSymbolAddress((void**)&edge_c, g_edge_c);

    const int e4grid = (NE / 4 + 255) / 256;
    const int sgrid  = (N_NODES * 8 + 255) / 256;      // 8 lanes per node
    const int lngrid = (N_NODES * 32 + 255) / 256;

    // ---- Build both CSR orderings (reused by all 6 SpMMs); cvt fused in ----
    zero_cvt<<<NGRID, 256>>>(cnt_r, cnt_c, (const float4*)ego, (uint2*)ego_h);
    hist_kernel4<<<e4grid, 256>>>((const int4*)rows, (const int4*)cols, cnt_r, cnt_c);
    scan1_both<<<2 * NB, SCAN_B>>>(cnt_r, ptr_r, bsum_r, cnt_c, ptr_c, bsum_c);
    scan23_both<<<2 * NGRID, 256>>>(ptr_r, bsum_r, cur_r, ptr_c, bsum_c, cur_c, NGRID);
    fill_kernel4<<<e4grid, 256>>>((const int4*)rows, (const int4*)cols,
                                  (const float4*)vals, cur_r, cur_c, edge_r, edge_c);

    const uint4* egoh = (const uint4*)ego_h;
    uint4* tmp4 = (uint4*)tmp_h;
    uint4* h4   = (uint4*)hh;

    // ---- Layer 0: h0 = A * (A^T * ego) ----   (spmm0 = launch #6 -> profiled)
    spmm_gather_h8<false><<<sgrid, 256>>>(egoh, ptr_c, edge_c, tmp4);
    spmm_gather_h8<false><<<sgrid, 256>>>((const uint4*)tmp_h, ptr_r, edge_r, h4);

    // ---- Layer 1: h1 = A * (A^T * leaky(h0)) ----
    spmm_gather_h8<true ><<<sgrid, 256>>>((const uint4*)hh, ptr_c, edge_c, tmp4);
    spmm_gather_h8<false><<<sgrid, 256>>>((const uint4*)tmp_h, ptr_r, edge_r, h4);

    // ---- Layer 2: h2 = A * (A^T * leaky(h1)) ----
    spmm_gather_h8<true ><<<sgrid, 256>>>((const uint4*)hh, ptr_c, edge_c, tmp4);
    spmm_gather_h8<false><<<sgrid, 256>>>((const uint4*)tmp_h, ptr_r, edge_r, h4);

    // ---- out = LN(h2 * 2^24)*gamma + beta + ego ----
    ln_residual_kernel<<<lngrid, 256>>>((const __half2*)hh, (const float2*)ego,
                                        gamma, beta, (float2*)out);
}

// round 15
// speedup vs baseline: 1.0255x; 1.0255x over previous
#include <cuda_runtime.h>
#include <cuda_fp16.h>
#include <cstdint>

// Problem constants (match reference_code)
#define N_NODES 150000
#define DIM 64
#define NE 4800000
#define NE_PAD (NE + 8 * N_NODES)   // worst-case padded edge count (6.0M)
#define LN_EPS 1e-5f
#define LEAKY_SLOPE 0.5f
#define SCAN_B 1024
#define NB 147            // ceil(150000/1024)
#define NGRID 587         // ceil(150000/256)

// Per-SpMM scale folded into edge weights so fp16 intermediates never overflow.
// 6 SpMMs => final h is (1/16)^6 = 2^-24 of true value; LN kernel undoes it.
#define VAL_SCALE  0.0625f          // 1/16
#define UNSCALE    16777216.0f      // 2^24

// ---------------- device scratch (no allocation allowed) -------------------
__device__ __align__(16) __half g_tmp_h[(size_t)N_NODES * DIM];
__device__ __align__(16) __half g_hh   [(size_t)N_NODES * DIM];
__device__ __align__(16) __half g_ego_h[(size_t)N_NODES * DIM];

__device__ int  g_cnt_r[N_NODES], g_cnt_c[N_NODES];
__device__ int  g_ptr_r[N_NODES + 1], g_ptr_c[N_NODES + 1];   // padded, 8-aligned
__device__ int  g_cur_r[N_NODES], g_cur_c[N_NODES];
__device__ int  g_bsum_r[NB], g_bsum_c[NB];
// packed edges: {nbr:int, val_bits:int} = 8 B, 16-B aligned.
// Regions are padded to multiples of 8 edges; pad slots are NEVER written by
// fill and remain zero-initialized ({nbr=0, val=0.0f}) => exact no-op edges.
__device__ __align__(16) int2 g_edge_r[NE_PAD];
__device__ __align__(16) int2 g_edge_c[NE_PAD];

// ---------------------------------------------------------------------------
__global__ __launch_bounds__(256) void zero_counts(int* __restrict__ a, int* __restrict__ b) {
    int i = blockIdx.x * blockDim.x + threadIdx.x;
    if (i < N_NODES) { a[i] = 0; b[i] = 0; }
}

// histogram: 4 edges per thread via int4 loads
__global__ __launch_bounds__(256) void hist_kernel4(
    const int4* __restrict__ rows4, const int4* __restrict__ cols4,
    int* __restrict__ cnt_r, int* __restrict__ cnt_c)
{
    int i = blockIdx.x * blockDim.x + threadIdx.x;
    if (i >= NE / 4) return;
    int4 r = __ldg(rows4 + i);
    int4 c = __ldg(cols4 + i);
    atomicAdd(cnt_r + r.x, 1); atomicAdd(cnt_r + r.y, 1);
    atomicAdd(cnt_r + r.z, 1); atomicAdd(cnt_r + r.w, 1);
    atomicAdd(cnt_c + c.x, 1); atomicAdd(cnt_c + c.y, 1);
    atomicAdd(cnt_c + c.z, 1); atomicAdd(cnt_c + c.w, 1);
}

// per-block exclusive scan over PADDED counts ((cnt+7)&~7); both arrays in one
// launch (2*NB blocks). Regions become 8-aligned with 8-multiple lengths.
__global__ __launch_bounds__(SCAN_B) void scan1_both(
    const int* __restrict__ cnt_r, int* __restrict__ excl_r, int* __restrict__ bsum_r,
    const int* __restrict__ cnt_c, int* __restrict__ excl_c, int* __restrict__ bsum_c)
{
    const int which = blockIdx.x / NB;
    const int blk   = blockIdx.x - which * NB;
    const int* cnt  = which ? cnt_c  : cnt_r;
    int* excl       = which ? excl_c : excl_r;
    int* bsum       = which ? bsum_c : bsum_r;

    __shared__ int sh[SCAN_B];
    int tid = threadIdx.x;
    int i   = blk * SCAN_B + tid;
    int v   = (i < N_NODES) ? ((cnt[i] + 7) & ~7) : 0;   // padded count
    sh[tid] = v;
    __syncthreads();
    #pragma unroll
    for (int off = 1; off < SCAN_B; off <<= 1) {
        int t = (tid >= off) ? sh[tid - off] : 0;
        __syncthreads();
        sh[tid] += t;
        __syncthreads();
    }
    if (i < N_NODES) excl[i] = sh[tid] - v;
    if (tid == SCAN_B - 1) bsum[blk] = sh[tid];
}

// fused scan2+scan3: apply block offsets, init cursors (region start = real
// edges go first, pad stays zero), write ptr[N] = total padded edges.
__global__ __launch_bounds__(256) void scan23_both(
    int* __restrict__ excl_r, const int* __restrict__ bsum_r, int* __restrict__ cur_r,
    int* __restrict__ excl_c, const int* __restrict__ bsum_c, int* __restrict__ cur_c,
    int ngrid)
{
    const int which = blockIdx.x / ngrid;
    const int blk   = blockIdx.x - which * ngrid;
    int* excl       = which ? excl_c : excl_r;
    const int* bsum = which ? bsum_c : bsum_r;
    int* cursor     = which ? cur_c  : cur_r;

    __shared__ int sh[256];
    int tid = threadIdx.x;
    int v   = (tid < NB) ? __ldg(bsum + tid) : 0;
    sh[tid] = v;
    __syncthreads();
    #pragma unroll
    for (int off = 1; off < 256; off <<= 1) {
        int t = (tid >= off) ? sh[tid - off] : 0;
        __syncthreads();
        sh[tid] += t;
        __syncthreads();
    }
    int b   = (blk * 256) >> 10;               // constant within this chunk
    int add = sh[b] - __ldg(bsum + b);         // exclusive prefix of block b
    int i   = blk * 256 + tid;
    if (i < N_NODES) {
        int val = excl[i] + add;
        excl[i]   = val;
        cursor[i] = val;
    }
    if (blk == 0 && tid == 0) excl[N_NODES] = sh[NB - 1];  // total padded
}

// scatter packed edges (4 edges/thread); fold 1/16 scale into stored weight
__global__ __launch_bounds__(256) void fill_kernel4(
    const int4* __restrict__ rows4, const int4* __restrict__ cols4,
    const float4* __restrict__ vals4,
    int* __restrict__ cur_r, int* __restrict__ cur_c,
    int2* __restrict__ edge_r, int2* __restrict__ edge_c)
{
    int i = blockIdx.x * blockDim.x + threadIdx.x;
    if (i >= NE / 4) return;
    int4   r = __ldg(rows4 + i);
    int4   c = __ldg(cols4 + i);
    float4 v = __ldg(vals4 + i);
    int vx = __float_as_int(v.x * VAL_SCALE);
    int vy = __float_as_int(v.y * VAL_SCALE);
    int vz = __float_as_int(v.z * VAL_SCALE);
    int vw = __float_as_int(v.w * VAL_SCALE);

    edge_r[atomicAdd(cur_r + r.x, 1)] = make_int2(c.x, vx);
    edge_r[atomicAdd(cur_r + r.y, 1)] = make_int2(c.y, vy);
    edge_r[atomicAdd(cur_r + r.z, 1)] = make_int2(c.z, vz);
    edge_r[atomicAdd(cur_r + r.w, 1)] = make_int2(c.w, vw);
    edge_c[atomicAdd(cur_c + c.x, 1)] = make_int2(r.x, vx);
    edge_c[atomicAdd(cur_c + c.y, 1)] = make_int2(r.y, vy);
    edge_c[atomicAdd(cur_c + c.z, 1)] = make_int2(r.z, vz);
    edge_c[atomicAdd(cur_c + c.w, 1)] = make_int2(r.w, vw);
}

// ---------------------------------------------------------------------------
__global__ __launch_bounds__(256) void cvt_f32_f16(
    const float4* __restrict__ in, uint2* __restrict__ out, int n4)
{
    int i = blockIdx.x * blockDim.x + threadIdx.x;
    if (i >= n4) return;
    float4 f = __ldg(in + i);
    __half2 a = __floats2half2_rn(f.x, f.y);
    __half2 b = __floats2half2_rn(f.z, f.w);
    uint2 o;
    o.x = *reinterpret_cast<unsigned int*>(&a);
    o.y = *reinterpret_cast<unsigned int*>(&b);
    out[i] = o;
}

// ---------------------------------------------------------------------------
// Core per-edge accumulate: 16 B (8 halves) -> 8 fp32 accs
// ---------------------------------------------------------------------------
__device__ __forceinline__ void accum_u4(uint4 p, float v, bool leaky, float* a) {
    __half2 h0 = *reinterpret_cast<__half2*>(&p.x);
    __half2 h1 = *reinterpret_cast<__half2*>(&p.y);
    __half2 h2 = *reinterpret_cast<__half2*>(&p.z);
    __half2 h3 = *reinterpret_cast<__half2*>(&p.w);
    if (leaky) {
        const __half2 h05 = __float2half2_rn(LEAKY_SLOPE);
        h0 = __hmax2(h0, __hmul2(h0, h05));
        h1 = __hmax2(h1, __hmul2(h1, h05));
        h2 = __hmax2(h2, __hmul2(h2, h05));
        h3 = __hmax2(h3, __hmul2(h3, h05));
    }
    float2 f0 = __half22float2(h0);
    float2 f1 = __half22float2(h1);
    float2 f2 = __half22float2(h2);
    float2 f3 = __half22float2(h3);
    a[0] = fmaf(v, f0.x, a[0]);
    a[1] = fmaf(v, f0.y, a[1]);
    a[2] = fmaf(v, f1.x, a[2]);
    a[3] = fmaf(v, f1.y, a[3]);
    a[4] = fmaf(v, f2.x, a[4]);
    a[5] = fmaf(v, f2.y, a[5]);
    a[6] = fmaf(v, f3.x, a[6]);
    a[7] = fmaf(v, f3.y, a[7]);
}

// ---------------------------------------------------------------------------
// Gather SpMM (fp16 node data, fp32 accumulate):
//   8 lanes per node, each lane owns 16 B (8 halves). Regions are 8-aligned
//   with 8-multiple lengths (zero pad edges) -> single branch-free 8-edge
//   loop, no peel, no tails, no intra-warp tail divergence.
// ---------------------------------------------------------------------------
template <bool LEAKY_IN>
__global__ __launch_bounds__(256) void spmm_gather_h8(
    const uint4* __restrict__ x,       // fp16 rows: node*8 + lane (16 B lanes)
    const int*   __restrict__ ptr,     // N+1 entries, 8-aligned regions
    const int2*  __restrict__ edges,
    uint4*       __restrict__ y)
{
    int t    = blockIdx.x * blockDim.x + threadIdx.x;
    int node = t >> 3;
    int lane = t & 7;
    if (node >= N_NODES) return;

    int beg = __ldg(ptr + node);
    int end = __ldg(ptr + node + 1);

    float acc[8] = {0.f, 0.f, 0.f, 0.f, 0.f, 0.f, 0.f, 0.f};

    for (int j = beg; j < end; j += 8) {
        int4 ea = __ldg(reinterpret_cast<const int4*>(edges + j));
        int4 eb = __ldg(reinterpret_cast<const int4*>(edges + j + 2));
        int4 ec = __ldg(reinterpret_cast<const int4*>(edges + j + 4));
        int4 ed = __ldg(reinterpret_cast<const int4*>(edges + j + 6));
        uint4 p0 = __ldg(x + ea.x * 8 + lane);
        uint4 p1 = __ldg(x + ea.z * 8 + lane);
        uint4 p2 = __ldg(x + eb.x * 8 + lane);
        uint4 p3 = __ldg(x + eb.z * 8 + lane);
        uint4 p4 = __ldg(x + ec.x * 8 + lane);
        uint4 p5 = __ldg(x + ec.z * 8 + lane);
        uint4 p6 = __ldg(x + ed.x * 8 + lane);
        uint4 p7 = __ldg(x + ed.z * 8 + lane);
        accum_u4(p0, __int_as_float(ea.y), LEAKY_IN, acc);
        accum_u4(p1, __int_as_float(ea.w), LEAKY_IN, acc);
        accum_u4(p2, __int_as_float(eb.y), LEAKY_IN, acc);
        accum_u4(p3, __int_as_float(eb.w), LEAKY_IN, acc);
        accum_u4(p4, __int_as_float(ec.y), LEAKY_IN, acc);
        accum_u4(p5, __int_as_float(ec.w), LEAKY_IN, acc);
        accum_u4(p6, __int_as_float(ed.y), LEAKY_IN, acc);
        accum_u4(p7, __int_as_float(ed.w), LEAKY_IN, acc);
    }

    __half2 o0 = __floats2half2_rn(acc[0], acc[1]);
    __half2 o1 = __floats2half2_rn(acc[2], acc[3]);
    __half2 o2 = __floats2half2_rn(acc[4], acc[5]);
    __half2 o3 = __floats2half2_rn(acc[6], acc[7]);
    uint4 o;
    o.x = *reinterpret_cast<unsigned int*>(&o0);
    o.y = *reinterpret_cast<unsigned int*>(&o1);
    o.z = *reinterpret_cast<unsigned int*>(&o2);
    o.w = *reinterpret_cast<unsigned int*>(&o3);
    y[node * 8 + lane] = o;
}

// ---------------------------------------------------------------------------
// Final: out = LN(h * 2^24) * gamma + beta + ego   (warp per node, D=64)
// ---------------------------------------------------------------------------
__global__ __launch_bounds__(256) void ln_residual_kernel(
    const __half2* __restrict__ h,
    const float2*  __restrict__ ego,
    const float*   __restrict__ gamma,
    const float*   __restrict__ beta,
    float2*        __restrict__ out)
{
    int gt   = blockIdx.x * blockDim.x + threadIdx.x;
    int node = gt >> 5;
    int lane = threadIdx.x & 31;
    if (node >= N_NODES) return;

    int idx = node * 32 + lane;
    float2 v = __half22float2(h[idx]);
    v.x *= UNSCALE;
    v.y *= UNSCALE;

    float s = v.x + v.y;
    #pragma unroll
    for (int o = 16; o; o >>= 1) s += __shfl_xor_sync(0xFFFFFFFFu, s, o);
    float mu = s * (1.f / 64.f);

    float dx = v.x - mu, dy = v.y - mu;
    float q = dx * dx + dy * dy;
    #pragma unroll
    for (int o = 16; o; o >>= 1) q += __shfl_xor_sync(0xFFFFFFFFu, q, o);
    float rstd = rsqrtf(q * (1.f / 64.f) + LN_EPS);

    float2 g = __ldg((const float2*)gamma + lane);
    float2 b = __ldg((const float2*)beta  + lane);
    float2 r = ego[idx];

    float2 o2;
    o2.x = dx * rstd * g.x + b.x + r.x;
    o2.y = dy * rstd * g.y + b.y + r.y;
    out[idx] = o2;
}

// ---------------------------------------------------------------------------
extern "C" void kernel_launch(void* const* d_in, const int* in_sizes, int n_in,
                              void* d_out, int out_size)
{
    const float* ego   = (const float*)d_in[0];
    const float* vals  = (const float*)d_in[1];
    const float* gamma = (const float*)d_in[2];
    const float* beta  = (const float*)d_in[3];
    const int*   rows  = (const int*)d_in[4];
    const int*   cols  = (const int*)d_in[5];
    float*       out   = (float*)d_out;

    void *tmp_h, *hh, *ego_h;
    int *cnt_r, *cnt_c, *ptr_r, *ptr_c, *cur_r, *cur_c, *bsum_r, *bsum_c;
    int2 *edge_r, *edge_c;
    cudaGetSymbolAddress(&tmp_h, g_tmp_h);
    cudaGetSymbolAddress(&hh,    g_hh);
    cudaGetSymbolAddress(&ego_h, g_ego_h);
    cudaGetSymbolAddress((void**)&cnt_r,  g_cnt_r);
    cudaGetSymbolAddress((void**)&cnt_c,  g_cnt_c);
    cudaGetSymbolAddress((void**)&ptr_r,  g_ptr_r);
    cudaGetSymbolAddress((void**)&ptr_c,  g_ptr_c);
    cudaGetSymbolAddress((void**)&cur_r,  g_cur_r);
    cudaGetSymbolAddress((void**)&cur_c,  g_cur_c);
    cudaGetSymbolAddress((void**)&bsum_r, g_bsum_r);
    cudaGetSymbolAddress((void**)&bsum_c, g_bsum_c);
    cudaGetSymbolAddress((void**)&edge_r, g_edge_r);
    cudaGetSymbolAddress((void**)&edge_c, g_edge_c);

    const int e4grid = (NE / 4 + 255) / 256;
    const int sgrid  = (N_NODES * 8 + 255) / 256;      // 8 lanes per node
    const int lngrid = (N_NODES * 32 + 255) / 256;
    const int cvt_n4 = N_NODES * DIM / 4;
    const int cgrid  = (cvt_n4 + 255) / 256;

    // ---- Build both padded CSR orderings (reused by all 6 SpMMs) ----
    zero_counts<<<NGRID, 256>>>(cnt_r, cnt_c);
    hist_kernel4<<<e4grid, 256>>>((const int4*)rows, (const int4*)cols, cnt_r, cnt_c);
    scan1_both<<<2 * NB, SCAN_B>>>(cnt_r, ptr_r, bsum_r, cnt_c, ptr_c, bsum_c);
    scan23_both<<<2 * NGRID, 256>>>(ptr_r, bsum_r, cur_r, ptr_c, bsum_c, cur_c, NGRID);
    fill_kernel4<<<e4grid, 256>>>((const int4*)rows, (const int4*)cols,
                                  (const float4*)vals, cur_r, cur_c, edge_r, edge_c);

    // ---- ego -> fp16 ----
    cvt_f32_f16<<<cgrid, 256>>>((const float4*)ego, (uint2*)ego_h, cvt_n4);

    const uint4* egoh = (const uint4*)ego_h;
    uint4* tmp4 = (uint4*)tmp_h;
    uint4* h4   = (uint4*)hh;

    // ---- Layer 0: h0 = A * (A^T * ego) ----
    spmm_gather_h8<false><<<sgrid, 256>>>(egoh, ptr_c, edge_c, tmp4);
    spmm_gather_h8<false><<<sgrid, 256>>>((const uint4*)tmp_h, ptr_r, edge_r, h4);

    // ---- Layer 1: h1 = A * (A^T * leaky(h0)) ----
    spmm_gather_h8<true ><<<sgrid, 256>>>((const uint4*)hh, ptr_c, edge_c, tmp4);
    spmm_gather_h8<false><<<sgrid, 256>>>((const uint4*)tmp_h, ptr_r, edge_r, h4);

    // ---- Layer 2: h2 = A * (A^T * leaky(h1)) ----
    spmm_gather_h8<true ><<<sgrid, 256>>>((const uint4*)hh, ptr_c, edge_c, tmp4);
    spmm_gather_h8<false><<<sgrid, 256>>>((const uint4*)tmp_h, ptr_r, edge_r, h4);

    // ---- out = LN(h2 * 2^24)*gamma + beta + ego ----
    ln_residual_kernel<<<lngrid, 256>>>((const __half2*)hh, (const float2*)ego,
                                        gamma, beta, (float2*)out);
}

// round 16
// speedup vs baseline: 1.0461x; 1.0201x over previous
#include <cuda_runtime.h>
#include <cuda_fp16.h>
#include <cstdint>

// Problem constants (match reference_code)
#define N_NODES 150000
#define DIM 64
#define NE 4800000
#define LN_EPS 1e-5f
#define LEAKY_SLOPE 0.5f
#define SCAN_B 1024
#define NB 147            // ceil(150000/1024)
#define NGRID 587         // ceil(150000/256)

// Per-SpMM scale folded into edge weights so fp16 intermediates never overflow.
// 6 SpMMs => final h is (1/16)^6 = 2^-24 of true value; LN kernel undoes it.
#define VAL_SCALE  0.0625f          // 1/16
#define UNSCALE    16777216.0f      // 2^24

// ---------------- device scratch (no allocation allowed) -------------------
__device__ __align__(16) __half g_tmp_h[(size_t)N_NODES * DIM];
__device__ __align__(16) __half g_hh   [(size_t)N_NODES * DIM];
__device__ __align__(16) __half g_ego_h[(size_t)N_NODES * DIM];

__device__ int  g_cnt_r[N_NODES], g_cnt_c[N_NODES];
__device__ int  g_ptr_r[N_NODES + 1], g_ptr_c[N_NODES + 1];   // ptr[N] = NE
__device__ int  g_cur_r[N_NODES], g_cur_c[N_NODES];
__device__ int  g_bsum_r[NB], g_bsum_c[NB];
// packed edges: {nbr:int, val_bits:int} = 8 B, 16-B aligned so int4 covers 2 edges
__device__ __align__(16) int2 g_edge_r[NE];
__device__ __align__(16) int2 g_edge_c[NE];

// ---------------------------------------------------------------------------
__global__ __launch_bounds__(256) void zero_counts(int* __restrict__ a, int* __restrict__ b) {
    int i = blockIdx.x * blockDim.x + threadIdx.x;
    if (i < N_NODES) { a[i] = 0; b[i] = 0; }
}

// histogram: 4 edges per thread via int4 loads
__global__ __launch_bounds__(256) void hist_kernel4(
    const int4* __restrict__ rows4, const int4* __restrict__ cols4,
    int* __restrict__ cnt_r, int* __restrict__ cnt_c)
{
    int i = blockIdx.x * blockDim.x + threadIdx.x;
    if (i >= NE / 4) return;
    int4 r = __ldg(rows4 + i);
    int4 c = __ldg(cols4 + i);
    atomicAdd(cnt_r + r.x, 1); atomicAdd(cnt_r + r.y, 1);
    atomicAdd(cnt_r + r.z, 1); atomicAdd(cnt_r + r.w, 1);
    atomicAdd(cnt_c + c.x, 1); atomicAdd(cnt_c + c.y, 1);
    atomicAdd(cnt_c + c.z, 1); atomicAdd(cnt_c + c.w, 1);
}

// per-block exclusive scan; handles BOTH cnt arrays in one launch (2*NB blocks)
__global__ __launch_bounds__(SCAN_B) void scan1_both(
    const int* __restrict__ cnt_r, int* __restrict__ excl_r, int* __restrict__ bsum_r,
    const int* __restrict__ cnt_c, int* __restrict__ excl_c, int* __restrict__ bsum_c)
{
    const int which = blockIdx.x / NB;
    const int blk   = blockIdx.x - which * NB;
    const int* cnt  = which ? cnt_c  : cnt_r;
    int* excl       = which ? excl_c : excl_r;
    int* bsum       = which ? bsum_c : bsum_r;

    __shared__ int sh[SCAN_B];
    int tid = threadIdx.x;
    int i   = blk * SCAN_B + tid;
    int v   = (i < N_NODES) ? cnt[i] : 0;
    sh[tid] = v;
    __syncthreads();
    #pragma unroll
    for (int off = 1; off < SCAN_B; off <<= 1) {
        int t = (tid >= off) ? sh[tid - off] : 0;
        __syncthreads();
        sh[tid] += t;
        __syncthreads();
    }
    if (i < N_NODES) excl[i] = sh[tid] - v;
    if (tid == SCAN_B - 1) bsum[blk] = sh[tid];
}

// fused scan2+scan3: every 256-node chunk redundantly scans the 147 block
// sums in shared (chunks never straddle a 1024 boundary -> single offset),
// then applies it and initializes the fill cursor. Also writes ptr[N]=NE.
__global__ __launch_bounds__(256) void scan23_both(
    int* __restrict__ excl_r, const int* __restrict__ bsum_r, int* __restrict__ cur_r,
    int* __restrict__ excl_c, const int* __restrict__ bsum_c, int* __restrict__ cur_c,
    int ngrid)
{
    const int which = blockIdx.x / ngrid;
    const int blk   = blockIdx.x - which * ngrid;
    int* excl       = which ? excl_c : excl_r;
    const int* bsum = which ? bsum_c : bsum_r;
    int* cursor     = which ? cur_c  : cur_r;

    __shared__ int sh[256];
    int tid = threadIdx.x;
    int v   = (tid < NB) ? __ldg(bsum + tid) : 0;
    sh[tid] = v;
    __syncthreads();
    #pragma unroll
    for (int off = 1; off < 256; off <<= 1) {
        int t = (tid >= off) ? sh[tid - off] : 0;
        __syncthreads();
        sh[tid] += t;
        __syncthreads();
    }
    int b   = (blk * 256) >> 10;               // constant within this chunk
    int add = sh[b] - __ldg(bsum + b);         // exclusive prefix of block b
    int i   = blk * 256 + tid;
    if (i < N_NODES) {
        int val = excl[i] + add;
        excl[i]   = val;
        cursor[i] = val;
    }
    if (blk == 0 && tid == 0) excl[N_NODES] = NE;   // sentinel: ptr[N] = NE
}

// scatter packed edges (4 edges/thread); fold 1/16 scale into stored weight
__global__ __launch_bounds__(256) void fill_kernel4(
    const int4* __restrict__ rows4, const int4* __restrict__ cols4,
    const float4* __restrict__ vals4,
    int* __restrict__ cur_r, int* __restrict__ cur_c,
    int2* __restrict__ edge_r, int2* __restrict__ edge_c)
{
    int i = blockIdx.x * blockDim.x + threadIdx.x;
    if (i >= NE / 4) return;
    int4   r = __ldg(rows4 + i);
    int4   c = __ldg(cols4 + i);
    float4 v = __ldg(vals4 + i);
    int vx = __float_as_int(v.x * VAL_SCALE);
    int vy = __float_as_int(v.y * VAL_SCALE);
    int vz = __float_as_int(v.z * VAL_SCALE);
    int vw = __float_as_int(v.w * VAL_SCALE);

    edge_r[atomicAdd(cur_r + r.x, 1)] = make_int2(c.x, vx);
    edge_r[atomicAdd(cur_r + r.y, 1)] = make_int2(c.y, vy);
    edge_r[atomicAdd(cur_r + r.z, 1)] = make_int2(c.z, vz);
    edge_r[atomicAdd(cur_r + r.w, 1)] = make_int2(c.w, vw);
    edge_c[atomicAdd(cur_c + c.x, 1)] = make_int2(r.x, vx);
    edge_c[atomicAdd(cur_c + c.y, 1)] = make_int2(r.y, vy);
    edge_c[atomicAdd(cur_c + c.z, 1)] = make_int2(r.z, vz);
    edge_c[atomicAdd(cur_c + c.w, 1)] = make_int2(r.w, vw);
}

// ---------------------------------------------------------------------------
__global__ __launch_bounds__(256) void cvt_f32_f16(
    const float4* __restrict__ in, uint2* __restrict__ out, int n4)
{
    int i = blockIdx.x * blockDim.x + threadIdx.x;
    if (i >= n4) return;
    float4 f = __ldg(in + i);
    __half2 a = __floats2half2_rn(f.x, f.y);
    __half2 b = __floats2half2_rn(f.z, f.w);
    uint2 o;
    o.x = *reinterpret_cast<unsigned int*>(&a);
    o.y = *reinterpret_cast<unsigned int*>(&b);
    out[i] = o;
}

// ---------------------------------------------------------------------------
// Core per-edge accumulate: 16 B (8 halves) -> 8 fp32 accs
// ---------------------------------------------------------------------------
__device__ __forceinline__ void accum_u4(uint4 p, float v, bool leaky, float* a) {
    __half2 h0 = *reinterpret_cast<__half2*>(&p.x);
    __half2 h1 = *reinterpret_cast<__half2*>(&p.y);
    __half2 h2 = *reinterpret_cast<__half2*>(&p.z);
    __half2 h3 = *reinterpret_cast<__half2*>(&p.w);
    if (leaky) {
        const __half2 h05 = __float2half2_rn(LEAKY_SLOPE);
        h0 = __hmax2(h0, __hmul2(h0, h05));
        h1 = __hmax2(h1, __hmul2(h1, h05));
        h2 = __hmax2(h2, __hmul2(h2, h05));
        h3 = __hmax2(h3, __hmul2(h3, h05));
    }
    float2 f0 = __half22float2(h0);
    float2 f1 = __half22float2(h1);
    float2 f2 = __half22float2(h2);
    float2 f3 = __half22float2(h3);
    a[0] = fmaf(v, f0.x, a[0]);
    a[1] = fmaf(v, f0.y, a[1]);
    a[2] = fmaf(v, f1.x, a[2]);
    a[3] = fmaf(v, f1.y, a[3]);
    a[4] = fmaf(v, f2.x, a[4]);
    a[5] = fmaf(v, f2.y, a[5]);
    a[6] = fmaf(v, f3.x, a[6]);
    a[7] = fmaf(v, f3.y, a[7]);
}

// ---------------------------------------------------------------------------
// Gather SpMM (fp16 node data, fp32 accumulate) — champion configuration:
//   8 lanes per node, each lane owns 16 B (8 halves); 8-edge unrolled loop
//   -> up to 8 concurrent gathers per node-group, 32 per warp.
// ---------------------------------------------------------------------------
template <bool LEAKY_IN>
__global__ __launch_bounds__(256) void spmm_gather_h8(
    const uint4* __restrict__ x,       // fp16 rows: node*8 + lane (16 B lanes)
    const int*   __restrict__ ptr,     // N+1 entries (ptr[N] = NE)
    const int2*  __restrict__ edges,
    uint4*       __restrict__ y)
{
    int t    = blockIdx.x * blockDim.x + threadIdx.x;
    int node = t >> 3;
    int lane = t & 7;
    if (node >= N_NODES) return;

    int beg = __ldg(ptr + node);
    int end = __ldg(ptr + node + 1);

    float acc[8] = {0.f, 0.f, 0.f, 0.f, 0.f, 0.f, 0.f, 0.f};

    int j = beg;
    // peel to even index so int4 (2-edge) loads are 16-B aligned
    if ((j & 1) && j < end) {
        int2 e = __ldg(edges + j);
        uint4 p = __ldg(x + e.x * 8 + lane);
        accum_u4(p, __int_as_float(e.y), LEAKY_IN, acc);
        ++j;
    }
    // 8-edge unroll: 4 aligned int4 edge loads + 8 independent gathers in flight
    for (; j + 8 <= end; j += 8) {
        int4 ea = __ldg(reinterpret_cast<const int4*>(edges + j));
        int4 eb = __ldg(reinterpret_cast<const int4*>(edges + j + 2));
        int4 ec = __ldg(reinterpret_cast<const int4*>(edges + j + 4));
        int4 ed = __ldg(reinterpret_cast<const int4*>(edges + j + 6));
        uint4 p0 = __ldg(x + ea.x * 8 + lane);
        uint4 p1 = __ldg(x + ea.z * 8 + lane);
        uint4 p2 = __ldg(x + eb.x * 8 + lane);
        uint4 p3 = __ldg(x + eb.z * 8 + lane);
        uint4 p4 = __ldg(x + ec.x * 8 + lane);
        uint4 p5 = __ldg(x + ec.z * 8 + lane);
        uint4 p6 = __ldg(x + ed.x * 8 + lane);
        uint4 p7 = __ldg(x + ed.z * 8 + lane);
        accum_u4(p0, __int_as_float(ea.y), LEAKY_IN, acc);
        accum_u4(p1, __int_as_float(ea.w), LEAKY_IN, acc);
        accum_u4(p2, __int_as_float(eb.y), LEAKY_IN, acc);
        accum_u4(p3, __int_as_float(eb.w), LEAKY_IN, acc);
        accum_u4(p4, __int_as_float(ec.y), LEAKY_IN, acc);
        accum_u4(p5, __int_as_float(ec.w), LEAKY_IN, acc);
        accum_u4(p6, __int_as_float(ed.y), LEAKY_IN, acc);
        accum_u4(p7, __int_as_float(ed.w), LEAKY_IN, acc);
    }
    if (j + 4 <= end) {
        int4 ea = __ldg(reinterpret_cast<const int4*>(edges + j));
        int4 eb = __ldg(reinterpret_cast<const int4*>(edges + j + 2));
        uint4 p0 = __ldg(x + ea.x * 8 + lane);
        uint4 p1 = __ldg(x + ea.z * 8 + lane);
        uint4 p2 = __ldg(x + eb.x * 8 + lane);
        uint4 p3 = __ldg(x + eb.z * 8 + lane);
        accum_u4(p0, __int_as_float(ea.y), LEAKY_IN, acc);
        accum_u4(p1, __int_as_float(ea.w), LEAKY_IN, acc);
        accum_u4(p2, __int_as_float(eb.y), LEAKY_IN, acc);
        accum_u4(p3, __int_as_float(eb.w), LEAKY_IN, acc);
        j += 4;
    }
    if (j + 2 <= end) {
        int4 ea = __ldg(reinterpret_cast<const int4*>(edges + j));
        uint4 p0 = __ldg(x + ea.x * 8 + lane);
        uint4 p1 = __ldg(x + ea.z * 8 + lane);
        accum_u4(p0, __int_as_float(ea.y), LEAKY_IN, acc);
        accum_u4(p1, __int_as_float(ea.w), LEAKY_IN, acc);
        j += 2;
    }
    if (j < end) {
        int2 e = __ldg(edges + j);
        uint4 p = __ldg(x + e.x * 8 + lane);
        accum_u4(p, __int_as_float(e.y), LEAKY_IN, acc);
    }

    __half2 o0 = __floats2half2_rn(acc[0], acc[1]);
    __half2 o1 = __floats2half2_rn(acc[2], acc[3]);
    __half2 o2 = __floats2half2_rn(acc[4], acc[5]);
    __half2 o3 = __floats2half2_rn(acc[6], acc[7]);
    uint4 o;
    o.x = *reinterpret_cast<unsigned int*>(&o0);
    o.y = *reinterpret_cast<unsigned int*>(&o1);
    o.z = *reinterpret_cast<unsigned int*>(&o2);
    o.w = *reinterpret_cast<unsigned int*>(&o3);
    y[node * 8 + lane] = o;
}

// ---------------------------------------------------------------------------
// Final: out = LN(h * 2^24) * gamma + beta + ego   (warp per node, D=64)
// ---------------------------------------------------------------------------
__global__ __launch_bounds__(256) void ln_residual_kernel(
    const __half2* __restrict__ h,
    const float2*  __restrict__ ego,
    const float*   __restrict__ gamma,
    const float*   __restrict__ beta,
    float2*        __restrict__ out)
{
    int gt   = blockIdx.x * blockDim.x + threadIdx.x;
    int node = gt >> 5;
    int lane = threadIdx.x & 31;
    if (node >= N_NODES) return;

    int idx = node * 32 + lane;
    float2 v = __half22float2(h[idx]);
    v.x *= UNSCALE;
    v.y *= UNSCALE;

    float s = v.x + v.y;
    #pragma unroll
    for (int o = 16; o; o >>= 1) s += __shfl_xor_sync(0xFFFFFFFFu, s, o);
    float mu = s * (1.f / 64.f);

    float dx = v.x - mu, dy = v.y - mu;
    float q = dx * dx + dy * dy;
    #pragma unroll
    for (int o = 16; o; o >>= 1) q += __shfl_xor_sync(0xFFFFFFFFu, q, o);
    float rstd = rsqrtf(q * (1.f / 64.f) + LN_EPS);

    float2 g = __ldg((const float2*)gamma + lane);
    float2 b = __ldg((const float2*)beta  + lane);
    float2 r = ego[idx];

    float2 o2;
    o2.x = dx * rstd * g.x + b.x + r.x;
    o2.y = dy * rstd * g.y + b.y + r.y;
    out[idx] = o2;
}

// ---------------------------------------------------------------------------
extern "C" void kernel_launch(void* const* d_in, const int* in_sizes, int n_in,
                              void* d_out, int out_size)
{
    const float* ego   = (const float*)d_in[0];
    const float* vals  = (const float*)d_in[1];
    const float* gamma = (const float*)d_in[2];
    const float* beta  = (const float*)d_in[3];
    const int*   rows  = (const int*)d_in[4];
    const int*   cols  = (const int*)d_in[5];
    float*       out   = (float*)d_out;

    void *tmp_h, *hh, *ego_h;
    int *cnt_r, *cnt_c, *ptr_r, *ptr_c, *cur_r, *cur_c, *bsum_r, *bsum_c;
    int2 *edge_r, *edge_c;
    cudaGetSymbolAddress(&tmp_h, g_tmp_h);
    cudaGetSymbolAddress(&hh,    g_hh);
    cudaGetSymbolAddress(&ego_h, g_ego_h);
    cudaGetSymbolAddress((void**)&cnt_r,  g_cnt_r);
    cudaGetSymbolAddress((void**)&cnt_c,  g_cnt_c);
    cudaGetSymbolAddress((void**)&ptr_r,  g_ptr_r);
    cudaGetSymbolAddress((void**)&ptr_c,  g_ptr_c);
    cudaGetSymbolAddress((void**)&cur_r,  g_cur_r);
    cudaGetSymbolAddress((void**)&cur_c,  g_cur_c);
    cudaGetSymbolAddress((void**)&bsum_r, g_bsum_r);
    cudaGetSymbolAddress((void**)&bsum_c, g_bsum_c);
    cudaGetSymbolAddress((void**)&edge_r, g_edge_r);
    cudaGetSymbolAddress((void**)&edge_c, g_edge_c);

    const int e4grid = (NE / 4 + 255) / 256;
    const int sgrid  = (N_NODES * 8 + 255) / 256;      // 8 lanes per node
    const int lngrid = (N_NODES * 32 + 255) / 256;
    const int cvt_n4 = N_NODES * DIM / 4;
    const int cgrid  = (cvt_n4 + 255) / 256;

    // ---- Build both CSR orderings (reused by all 6 SpMMs) ----
    zero_counts<<<NGRID, 256>>>(cnt_r, cnt_c);
    hist_kernel4<<<e4grid, 256>>>((const int4*)rows, (const int4*)cols, cnt_r, cnt_c);
    scan1_both<<<2 * NB, SCAN_B>>>(cnt_r, ptr_r, bsum_r, cnt_c, ptr_c, bsum_c);
    scan23_both<<<2 * NGRID, 256>>>(ptr_r, bsum_r, cur_r, ptr_c, bsum_c, cur_c, NGRID);
    fill_kernel4<<<e4grid, 256>>>((const int4*)rows, (const int4*)cols,
                                  (const float4*)vals, cur_r, cur_c, edge_r, edge_c);

    // ---- ego -> fp16 ----
    cvt_f32_f16<<<cgrid, 256>>>((const float4*)ego, (uint2*)ego_h, cvt_n4);

    const uint4* egoh = (const uint4*)ego_h;
    uint4* tmp4 = (uint4*)tmp_h;
    uint4* h4   = (uint4*)hh;

    // ---- Layer 0: h0 = A * (A^T * ego) ----
    spmm_gather_h8<false><<<sgrid, 256>>>(egoh, ptr_c, edge_c, tmp4);
    spmm_gather_h8<false><<<sgrid, 256>>>((const uint4*)tmp_h, ptr_r, edge_r, h4);

    // ---- Layer 1: h1 = A * (A^T * leaky(h0)) ----
    spmm_gather_h8<true ><<<sgrid, 256>>>((const uint4*)hh, ptr_c, edge_c, tmp4);
    spmm_gather_h8<false><<<sgrid, 256>>>((const uint4*)tmp_h, ptr_r, edge_r, h4);

    // ---- Layer 2: h2 = A * (A^T * leaky(h1)) ----
    spmm_gather_h8<true ><<<sgrid, 256>>>((const uint4*)hh, ptr_c, edge_c, tmp4);
    spmm_gather_h8<false><<<sgrid, 256>>>((const uint4*)tmp_h, ptr_r, edge_r, h4);

    // ---- out = LN(h2 * 2^24)*gamma + beta + ego ----
    ln_residual_kernel<<<lngrid, 256>>>((const __half2*)hh, (const float2*)ego,
                                        gamma, beta, (float2*)out);
}